// round 12
// baseline (speedup 1.0000x reference)
#include <cuda_runtime.h>
#include <cstdint>

// ---------------- problem constants ----------------
#define BB 16
#define TT 4096
#define DD 128
#define NC 9
#define CBN 1024
#define CD 8

#define NCOL (BB*TT)                  // 65536
#define ZQ_N (BB*DD*TT)               // 8388608
#define CODES_OFF (ZQ_N + 3)          // 8388611
#define CODES_N (BB*NC*TT)            // 589824
#define LAT_OFF (CODES_OFF + CODES_N) // 8978435

// ---------------- smem layout (float offsets) ----------------
// res[64][136], cb8[1024][8], cb2[1024], iw[8][132], ow[2][128][12],
// ib[8], obt[2][8][16], enc_t[8][68], scri u64[64][17], red[32]
#define RES_OFF  0
#define CB8_OFF  8704
#define CB2_OFF  16896
#define IW_OFF   17920
#define OW_OFF   18976
#define IB_OFF   22048
#define OBT_OFF  22056
#define ENC_OFF  22312
#define SCRI_OFF 22856
#define RED_OFF  25032
#define SMEM_FLOATS 25064
#define SMEM_BYTES (SMEM_FLOATS*4)    // 100256 B; x2 blocks = 200.5 KB <= 228 KB

// codebook scratch: rows = -2*cb_n (normalized), plus per-entry sum(cb_n^2)
__device__ __align__(16) float g_cb8[NC*CBN*8];
__device__ __align__(16) float g_cb2[NC*CBN];

typedef unsigned long long u64;

__device__ __forceinline__ u64 ffma2(u64 a, u64 b, u64 c){
    u64 d; asm("fma.rn.f32x2 %0, %1, %2, %3;" : "=l"(d) : "l"(a), "l"(b), "l"(c)); return d;
}
__device__ __forceinline__ u64 pack2(float lo, float hi){
    u64 d; asm("mov.b64 %0, {%1, %2};" : "=l"(d) : "f"(lo), "f"(hi)); return d;
}
__device__ __forceinline__ void unpack2(u64 a, float& lo, float& hi){
    asm("mov.b64 {%0, %1}, %2;" : "=f"(lo), "=f"(hi) : "l"(a));
}
// sortable key: ascending u64 order == ascending (score, entry-index)
__device__ __forceinline__ u64 mkkey(float s, int idx){
    unsigned u = __float_as_uint(s);
    u ^= ((unsigned)((int)u >> 31)) | 0x80000000u;
    return ((u64)u << 32) | (unsigned)idx;
}

// ---------------- prep: normalize codebooks (+ zero scalar outputs) ----------------
__global__ void rvq_prep(const float* __restrict__ cbk, float* __restrict__ out){
    if (blockIdx.x == 0 && threadIdx.x < 3) out[ZQ_N + threadIdx.x] = 0.f;
    int e = blockIdx.x * 256 + threadIdx.x;
    if (e >= NC*CBN) return;
    float v[8]; float s = 0.f;
    #pragma unroll
    for (int k = 0; k < 8; k++){ v[k] = cbk[(size_t)e*8 + k]; s += v[k]*v[k]; }
    float dnm = fmaxf(sqrtf(s), 1e-12f);
    float s2 = 0.f;
    #pragma unroll
    for (int k = 0; k < 8; k++){
        float w = v[k] / dnm;
        g_cb8[(size_t)e*8 + k] = -2.f * w;   // pre-scaled for the distance scan
        s2 += w*w;
    }
    g_cb2[e] = s2;
}

// stage params for codebook i (ow/ob double-buffered on i&1)
__device__ __forceinline__ void stage_params(int i, int tid, float* sm,
    const float* __restrict__ in_w, const float* __restrict__ in_b,
    const float* __restrict__ out_w, const float* __restrict__ out_b)
{
    float4* dst4 = (float4*)(sm + CB8_OFF);
    const float4* src4 = (const float4*)(g_cb8 + (size_t)i*CBN*8);
    #pragma unroll
    for (int k = 0; k < 4; k++) dst4[tid + k*512] = src4[tid + k*512];
    if (tid < 256)
        ((float4*)(sm + CB2_OFF))[tid] = ((const float4*)(g_cb2 + (size_t)i*CBN))[tid];
    #pragma unroll
    for (int k = 0; k < 2; k++){
        int idx = k*512 + tid;
        sm[IW_OFF + (idx>>7)*132 + (idx&127)] = in_w[(size_t)i*1024 + idx];
        sm[OW_OFF + (i&1)*1536 + (idx>>3)*12 + (idx&7)] = out_w[(size_t)i*1024 + idx];
    }
    if (tid < 8)   sm[IB_OFF + tid] = in_b[i*8 + tid];
    if (tid < 128) sm[OBT_OFF + (i&1)*128 + (tid&7)*16 + (tid>>3)] = out_b[i*128 + tid];
}

// ---------------- main kernel ----------------
// grid 1024 x 512 threads; block = 64 consecutive t-columns of one batch b.
__global__ __launch_bounds__(512, 2)
void rvq_main(const float* __restrict__ x, const float* __restrict__ noise,
              const float* __restrict__ in_w, const float* __restrict__ in_b,
              const float* __restrict__ cbk, const float* __restrict__ out_w,
              const float* __restrict__ out_b, float* __restrict__ out)
{
    extern __shared__ float sm[];
    float* res_s = sm + RES_OFF;
    float* cb8_s = sm + CB8_OFF;
    float* cb2_s = sm + CB2_OFF;
    float* enc_t = sm + ENC_OFF;
    u64*   scri  = (u64*)(sm + SCRI_OFF);
    float* red   = sm + RED_OFF;

    const int tid  = threadIdx.x;
    const int bidx = blockIdx.x;
    const int b    = bidx >> 6;
    const int t0   = (bidx & 63) * 64;
    const int lane = tid & 31;
    const int w    = tid >> 5;
    const int r    = lane & 3;     // column-within-warp
    const int q    = lane >> 2;    // codebook-dim / d-group
    const int c    = w*4 + r;      // this lane's column within block
    const int t    = t0 + c;

    float kl_acc = 0.f, loss_acc = 0.f;

    const float* xm = x + ((size_t)b*256)*TT;
    const float* xs = x + ((size_t)b*256 + 128)*TT;
    const float* nz = noise + ((size_t)b*128)*TT;

    // ---- prologue: stage codebook 0 + z init (coalesced) + KL ----
    stage_params(0, tid, sm, in_w, in_b, out_w, out_b);
    #pragma unroll
    for (int k = 0; k < 16; k++){
        int idx = k*512 + tid;
        int d = idx >> 6, cc = idx & 63;
        int tt = t0 + cc;
        float m  = xm[(size_t)d*TT + tt];
        float s  = xs[(size_t)d*TT + tt];
        float n  = nz[(size_t)d*TT + tt];
        float sp = fmaxf(s, 0.f) + log1pf(expf(-fabsf(s)));
        float st = sp + 1e-4f;
        float var = st*st;
        kl_acc += m*m + var - logf(var) - 1.f;
        res_s[cc*136 + d] = n*st + m;
    }
    __syncthreads();

    const u64 ZERO2 = pack2(0.f, 0.f);

    for (int i = 0; i < NC; i++){
        // ========== phase 1: in_proj + normalize + publish enc ==========
        float ze;
        {
            const ulonglong2* wr = (const ulonglong2*)(sm + IW_OFF + q*132);
            const ulonglong2* rr = (const ulonglong2*)(res_s + c*136);
            u64 a0 = ZERO2, a1 = ZERO2;
            #pragma unroll 8
            for (int k = 0; k < 32; k++){
                ulonglong2 wv = wr[k], rv = rr[k];
                a0 = ffma2(wv.x, rv.x, a0);
                a1 = ffma2(wv.y, rv.y, a1);
            }
            float l0,h0,l1,h1; unpack2(a0,l0,h0); unpack2(a1,l1,h1);
            ze = (l0+l1) + (h0+h1) + sm[IB_OFF + q];
        }
        float ss = ze*ze;
        ss += __shfl_xor_sync(0xffffffffu, ss, 4);
        ss += __shfl_xor_sync(0xffffffffu, ss, 8);
        ss += __shfl_xor_sync(0xffffffffu, ss, 16);
        float en = ze / fmaxf(sqrtf(ss), 1e-12f);

        enc_t[q*68 + c] = en;                               // 1-wf STS (4q+r perm)
        out[LAT_OFF + ((size_t)b*(NC*CD) + i*CD + q)*TT + t] = ze;
        __syncthreads();   // A

        // ========== phase 2: scan (warp w owns entries [64w,64w+64)) ==========
        {
            u64 eA[4], eB[4];
            #pragma unroll
            for (int k = 0; k < 4; k++){
                float a0 = enc_t[(2*k)*68 + lane],      a1 = enc_t[(2*k+1)*68 + lane];
                float b0 = enc_t[(2*k)*68 + lane + 32], b1 = enc_t[(2*k+1)*68 + lane + 32];
                eA[k] = pack2(a0, a1); eB[k] = pack2(b0, b1);
            }
            const float* base8 = cb8_s + (w*64)*8;
            const float* b2    = cb2_s + w*64;
            float bestA = 3.4e38f, bestB = 3.4e38f;
            int bjA = 0, bjB = 0;
            #pragma unroll 2
            for (int j4 = 0; j4 < 16; j4++){
                float4 s4 = *(const float4*)(b2 + j4*4);    // broadcast, 1 wf per 4 entries
                float s2a[4] = {s4.x, s4.y, s4.z, s4.w};
                #pragma unroll
                for (int m = 0; m < 4; m++){
                    int j = j4*4 + m;
                    const float* row = base8 + j*8;         // uniform -> broadcast
                    ulonglong2 p0 = *(const ulonglong2*)row;
                    ulonglong2 p1 = *(const ulonglong2*)(row + 4);
                    u64 c0 = pack2(s2a[m], 0.f);            // acc init = (sum cb_n^2, 0)

                    u64 aA = ffma2(p0.x, eA[0], c0);
                    aA = ffma2(p0.y, eA[1], aA);
                    aA = ffma2(p1.x, eA[2], aA);
                    aA = ffma2(p1.y, eA[3], aA);
                    float al, ah; unpack2(aA, al, ah);
                    float sA = al + ah;
                    if (sA < bestA){ bestA = sA; bjA = j; }

                    u64 aB = ffma2(p0.x, eB[0], c0);
                    aB = ffma2(p0.y, eB[1], aB);
                    aB = ffma2(p1.x, eB[2], aB);
                    aB = ffma2(p1.y, eB[3], aB);
                    float bl, bh; unpack2(aB, bl, bh);
                    float sB = bl + bh;
                    if (sB < bestB){ bestB = sB; bjB = j; }
                }
            }
            scri[lane*17 + w]      = mkkey(bestA, (w<<6) | bjA);
            scri[(lane+32)*17 + w] = mkkey(bestB, (w<<6) | bjB);
        }
        __syncthreads();   // B

        // ========== phase 3: per-warp argmin combine + outputs + out_proj (+ stage next) ==========
        int bi;
        {
            // lane (q,r): slot q and q+8 of column c = 4w+r
            const u64* sp = scri + (size_t)c*17;
            u64 m0 = sp[q], m1 = sp[q+8];
            u64 m  = (m1 < m0) ? m1 : m0;
            #pragma unroll
            for (int d2 = 4; d2 <= 16; d2 <<= 1){
                unsigned lo = __shfl_xor_sync(0xffffffffu, (unsigned)m, d2);
                unsigned hi = __shfl_xor_sync(0xffffffffu, (unsigned)(m >> 32), d2);
                u64 o = ((u64)hi << 32) | lo;
                if (o < m) m = o;
            }
            bi = (int)(unsigned)m;
        }

        float cbv = cbk[((size_t)i*CBN + bi)*8 + q];
        float diff = ze - cbv;
        loss_acc += diff*diff;
        if (q == 0) out[CODES_OFF + ((size_t)b*NC + i)*TT + t] = (float)bi;

        u64 stz2[4];
        #pragma unroll
        for (int m = 0; m < 4; m++){
            float lo = __shfl_sync(0xffffffffu, cbv, 8*m + r);
            float hi = __shfl_sync(0xffffffffu, cbv, 8*m + 4 + r);
            stz2[m] = pack2(lo, hi);
        }

        // out_proj + residual update (lane covers d = q + 8j); res stride 136 => conflict-free
        {
            const float* owb = sm + OW_OFF + (i&1)*1536 + q*12;
            const float* obb = sm + OBT_OFF + (i&1)*128 + q*16;
            float* rp = res_s + c*136 + q;
            #pragma unroll
            for (int m = 0; m < 4; m++){
                float4 ov = *(const float4*)(obb + 4*m);    // broadcast, 1 wf
                float obj[4] = {ov.x, ov.y, ov.z, ov.w};
                #pragma unroll
                for (int jj = 0; jj < 4; jj++){
                    int j = m*4 + jj;
                    const float* row = owb + j*96;
                    ulonglong2 p0 = *(const ulonglong2*)row;
                    ulonglong2 p1 = *(const ulonglong2*)(row + 4);
                    u64 acc = ffma2(p0.x, stz2[0], ZERO2);
                    acc = ffma2(p0.y, stz2[1], acc);
                    acc = ffma2(p1.x, stz2[2], acc);
                    acc = ffma2(p1.y, stz2[3], acc);
                    float ol, oh; unpack2(acc, ol, oh);
                    float o = (ol + oh) + obj[jj];
                    rp[8*j] -= o;
                }
            }
        }

        if (i < NC-1) stage_params(i+1, tid, sm, in_w, in_b, out_w, out_b);
        __syncthreads();   // C
    }

    // ---- z_q = z - residual_final (coalesced, z recomputed) ----
    #pragma unroll
    for (int k = 0; k < 16; k++){
        int idx = k*512 + tid;
        int d = idx >> 6, cc = idx & 63;
        int tt = t0 + cc;
        float m  = xm[(size_t)d*TT + tt];
        float s  = xs[(size_t)d*TT + tt];
        float n  = nz[(size_t)d*TT + tt];
        float sp = fmaxf(s, 0.f) + log1pf(expf(-fabsf(s)));
        float st = sp + 1e-4f;
        float z  = n*st + m;
        out[((size_t)b*DD + d)*TT + tt] = z - res_s[cc*136 + d];
    }

    // ---- loss reductions ----
    #pragma unroll
    for (int s2 = 1; s2 < 32; s2 <<= 1){
        kl_acc   += __shfl_xor_sync(0xffffffffu, kl_acc,   s2);
        loss_acc += __shfl_xor_sync(0xffffffffu, loss_acc, s2);
    }
    if (lane == 0){ red[w] = kl_acc; red[16 + w] = loss_acc; }
    __syncthreads();
    if (tid == 0){
        float ks = 0.f, ls = 0.f;
        #pragma unroll
        for (int j = 0; j < 16; j++){ ks += red[j]; ls += red[16 + j]; }
        atomicAdd(out + ZQ_N,     ks * (1.f / (float)(BB*TT)));
        float lv = ls * (1.f / (float)(BB*CD*TT*NC));
        atomicAdd(out + ZQ_N + 1, lv);   // commitment
        atomicAdd(out + ZQ_N + 2, lv);   // codebook (identical value)
    }
}

// ---------------- launch ----------------
extern "C" void kernel_launch(void* const* d_in, const int* in_sizes, int n_in,
                              void* d_out, int out_size)
{
    const float* x     = (const float*)d_in[0];
    const float* noise = (const float*)d_in[1];
    const float* in_w  = (const float*)d_in[2];
    const float* in_b  = (const float*)d_in[3];
    const float* cbk   = (const float*)d_in[4];
    const float* out_w = (const float*)d_in[5];
    const float* out_b = (const float*)d_in[6];
    float* out = (float*)d_out;

    cudaFuncSetAttribute(rvq_main, cudaFuncAttributeMaxDynamicSharedMemorySize, SMEM_BYTES);

    rvq_prep<<<(NC*CBN + 255)/256, 256>>>(cbk, out);
    rvq_main<<<NCOL/64, 512, SMEM_BYTES>>>(x, noise, in_w, in_b, cbk, out_w, out_b, out);
}

// round 13
// speedup vs baseline: 1.0006x; 1.0006x over previous
#include <cuda_runtime.h>
#include <cstdint>

// ---------------- problem constants ----------------
#define BB 16
#define TT 4096
#define DD 128
#define NC 9
#define CBN 1024
#define CD 8

#define NCOL (BB*TT)                  // 65536
#define ZQ_N (BB*DD*TT)               // 8388608
#define CODES_OFF (ZQ_N + 3)          // 8388611
#define CODES_N (BB*NC*TT)            // 589824
#define LAT_OFF (CODES_OFF + CODES_N) // 8978435

// ---------------- smem layout (float offsets) ----------------
// res[64][136], cb8[1024][8], cb2[1024], iw[8][132], ow[2][128][12],
// ib[8], obt[2][8][16], enc_t[8][68], scri u64[64][17], red[32]
#define RES_OFF  0
#define CB8_OFF  8704
#define CB2_OFF  16896
#define IW_OFF   17920
#define OW_OFF   18976
#define IB_OFF   22048
#define OBT_OFF  22056
#define ENC_OFF  22312
#define SCRI_OFF 22856
#define RED_OFF  25032
#define SMEM_FLOATS 25064
#define SMEM_BYTES (SMEM_FLOATS*4)    // 100256 B; x2 blocks = 200.5 KB <= 228 KB

// codebook scratch: rows = -2*cb_n (normalized), plus per-entry sum(cb_n^2)
__device__ __align__(16) float g_cb8[NC*CBN*8];
__device__ __align__(16) float g_cb2[NC*CBN];

typedef unsigned long long u64;

__device__ __forceinline__ u64 ffma2(u64 a, u64 b, u64 c){
    u64 d; asm("fma.rn.f32x2 %0, %1, %2, %3;" : "=l"(d) : "l"(a), "l"(b), "l"(c)); return d;
}
__device__ __forceinline__ u64 pack2(float lo, float hi){
    u64 d; asm("mov.b64 %0, {%1, %2};" : "=l"(d) : "f"(lo), "f"(hi)); return d;
}
__device__ __forceinline__ void unpack2(u64 a, float& lo, float& hi){
    asm("mov.b64 {%0, %1}, %2;" : "=f"(lo), "=f"(hi) : "l"(a));
}
// sortable key: ascending u64 order == ascending (score, entry-index)
__device__ __forceinline__ u64 mkkey(float s, int idx){
    unsigned u = __float_as_uint(s);
    u ^= ((unsigned)((int)u >> 31)) | 0x80000000u;
    return ((u64)u << 32) | (unsigned)idx;
}

// ---------------- prep: normalize codebooks (+ zero scalar outputs) ----------------
__global__ void rvq_prep(const float* __restrict__ cbk, float* __restrict__ out){
    if (blockIdx.x == 0 && threadIdx.x < 3) out[ZQ_N + threadIdx.x] = 0.f;
    int e = blockIdx.x * 256 + threadIdx.x;
    if (e >= NC*CBN) return;
    float v[8]; float s = 0.f;
    #pragma unroll
    for (int k = 0; k < 8; k++){ v[k] = cbk[(size_t)e*8 + k]; s += v[k]*v[k]; }
    float dnm = fmaxf(sqrtf(s), 1e-12f);
    float s2 = 0.f;
    #pragma unroll
    for (int k = 0; k < 8; k++){
        float w = v[k] / dnm;
        g_cb8[(size_t)e*8 + k] = -2.f * w;   // pre-scaled for the distance scan
        s2 += w*w;
    }
    g_cb2[e] = s2;
}

// stage params for codebook i (ow/ob double-buffered on i&1)
__device__ __forceinline__ void stage_params(int i, int tid, float* sm,
    const float* __restrict__ in_w, const float* __restrict__ in_b,
    const float* __restrict__ out_w, const float* __restrict__ out_b)
{
    float4* dst4 = (float4*)(sm + CB8_OFF);
    const float4* src4 = (const float4*)(g_cb8 + (size_t)i*CBN*8);
    #pragma unroll
    for (int k = 0; k < 4; k++) dst4[tid + k*512] = src4[tid + k*512];
    if (tid < 256)
        ((float4*)(sm + CB2_OFF))[tid] = ((const float4*)(g_cb2 + (size_t)i*CBN))[tid];
    #pragma unroll
    for (int k = 0; k < 2; k++){
        int idx = k*512 + tid;
        sm[IW_OFF + (idx>>7)*132 + (idx&127)] = in_w[(size_t)i*1024 + idx];
        sm[OW_OFF + (i&1)*1536 + (idx>>3)*12 + (idx&7)] = out_w[(size_t)i*1024 + idx];
    }
    if (tid < 8)   sm[IB_OFF + tid] = in_b[i*8 + tid];
    if (tid < 128) sm[OBT_OFF + (i&1)*128 + (tid&7)*16 + (tid>>3)] = out_b[i*128 + tid];
}

// ---------------- main kernel ----------------
// grid 1024 x 512 threads; block = 64 consecutive t-columns of one batch b.
__global__ __launch_bounds__(512, 2)
void rvq_main(const float* __restrict__ x, const float* __restrict__ noise,
              const float* __restrict__ in_w, const float* __restrict__ in_b,
              const float* __restrict__ cbk, const float* __restrict__ out_w,
              const float* __restrict__ out_b, float* __restrict__ out)
{
    extern __shared__ float sm[];
    float* res_s = sm + RES_OFF;
    float* cb8_s = sm + CB8_OFF;
    float* cb2_s = sm + CB2_OFF;
    float* enc_t = sm + ENC_OFF;
    u64*   scri  = (u64*)(sm + SCRI_OFF);
    float* red   = sm + RED_OFF;

    const int tid  = threadIdx.x;
    const int bidx = blockIdx.x;
    const int b    = bidx >> 6;
    const int t0   = (bidx & 63) * 64;
    const int lane = tid & 31;
    const int w    = tid >> 5;
    const int r    = lane & 3;     // column-within-warp
    const int q    = lane >> 2;    // codebook-dim / d-group
    const int c    = w*4 + r;      // this lane's column within block
    const int t    = t0 + c;

    float kl_acc = 0.f, loss_acc = 0.f;

    const float* xm = x + ((size_t)b*256)*TT;
    const float* xs = x + ((size_t)b*256 + 128)*TT;
    const float* nz = noise + ((size_t)b*128)*TT;

    // ---- prologue: stage codebook 0 + z init (coalesced) + KL ----
    stage_params(0, tid, sm, in_w, in_b, out_w, out_b);
    #pragma unroll
    for (int k = 0; k < 16; k++){
        int idx = k*512 + tid;
        int d = idx >> 6, cc = idx & 63;
        int tt = t0 + cc;
        float m  = xm[(size_t)d*TT + tt];
        float s  = xs[(size_t)d*TT + tt];
        float n  = nz[(size_t)d*TT + tt];
        float sp = fmaxf(s, 0.f) + log1pf(expf(-fabsf(s)));
        float st = sp + 1e-4f;
        float var = st*st;
        kl_acc += m*m + var - logf(var) - 1.f;
        res_s[cc*136 + d] = n*st + m;
    }
    __syncthreads();

    const u64 ZERO2 = pack2(0.f, 0.f);

    for (int i = 0; i < NC; i++){
        // ========== phase 1: in_proj + normalize + publish enc ==========
        float ze;
        {
            const ulonglong2* wr = (const ulonglong2*)(sm + IW_OFF + q*132);
            const ulonglong2* rr = (const ulonglong2*)(res_s + c*136);
            u64 a0 = ZERO2, a1 = ZERO2;
            #pragma unroll 8
            for (int k = 0; k < 32; k++){
                ulonglong2 wv = wr[k], rv = rr[k];
                a0 = ffma2(wv.x, rv.x, a0);
                a1 = ffma2(wv.y, rv.y, a1);
            }
            float l0,h0,l1,h1; unpack2(a0,l0,h0); unpack2(a1,l1,h1);
            ze = (l0+l1) + (h0+h1) + sm[IB_OFF + q];
        }
        float ss = ze*ze;
        ss += __shfl_xor_sync(0xffffffffu, ss, 4);
        ss += __shfl_xor_sync(0xffffffffu, ss, 8);
        ss += __shfl_xor_sync(0xffffffffu, ss, 16);
        float en = ze / fmaxf(sqrtf(ss), 1e-12f);

        enc_t[q*68 + c] = en;                               // 1-wf STS (4q+r perm)
        out[LAT_OFF + ((size_t)b*(NC*CD) + i*CD + q)*TT + t] = ze;
        __syncthreads();   // A

        // ========== phase 2: scan (warp w owns entries [64w,64w+64)) ==========
        {
            u64 eA[4], eB[4];
            #pragma unroll
            for (int k = 0; k < 4; k++){
                float a0 = enc_t[(2*k)*68 + lane],      a1 = enc_t[(2*k+1)*68 + lane];
                float b0 = enc_t[(2*k)*68 + lane + 32], b1 = enc_t[(2*k+1)*68 + lane + 32];
                eA[k] = pack2(a0, a1); eB[k] = pack2(b0, b1);
            }
            const float* base8 = cb8_s + (w*64)*8;
            const float* b2    = cb2_s + w*64;
            float bestA = 3.4e38f, bestB = 3.4e38f;
            int bjA = 0, bjB = 0;
            #pragma unroll 2
            for (int j4 = 0; j4 < 16; j4++){
                float4 s4 = *(const float4*)(b2 + j4*4);    // broadcast, 1 wf per 4 entries
                float s2a[4] = {s4.x, s4.y, s4.z, s4.w};
                #pragma unroll
                for (int m = 0; m < 4; m++){
                    int j = j4*4 + m;
                    const float* row = base8 + j*8;         // uniform -> broadcast
                    ulonglong2 p0 = *(const ulonglong2*)row;
                    ulonglong2 p1 = *(const ulonglong2*)(row + 4);
                    u64 c0 = pack2(s2a[m], 0.f);            // acc init = (sum cb_n^2, 0)

                    u64 aA = ffma2(p0.x, eA[0], c0);
                    aA = ffma2(p0.y, eA[1], aA);
                    aA = ffma2(p1.x, eA[2], aA);
                    aA = ffma2(p1.y, eA[3], aA);
                    float al, ah; unpack2(aA, al, ah);
                    float sA = al + ah;
                    if (sA < bestA){ bestA = sA; bjA = j; }

                    u64 aB = ffma2(p0.x, eB[0], c0);
                    aB = ffma2(p0.y, eB[1], aB);
                    aB = ffma2(p1.x, eB[2], aB);
                    aB = ffma2(p1.y, eB[3], aB);
                    float bl, bh; unpack2(aB, bl, bh);
                    float sB = bl + bh;
                    if (sB < bestB){ bestB = sB; bjB = j; }
                }
            }
            scri[lane*17 + w]      = mkkey(bestA, (w<<6) | bjA);
            scri[(lane+32)*17 + w] = mkkey(bestB, (w<<6) | bjB);
        }
        __syncthreads();   // B

        // ========== phase 3: per-warp argmin combine + outputs + out_proj (+ stage next) ==========
        int bi;
        {
            // lane (q,r): slot q and q+8 of column c = 4w+r
            const u64* sp = scri + (size_t)c*17;
            u64 m0 = sp[q], m1 = sp[q+8];
            u64 m  = (m1 < m0) ? m1 : m0;
            #pragma unroll
            for (int d2 = 4; d2 <= 16; d2 <<= 1){
                unsigned lo = __shfl_xor_sync(0xffffffffu, (unsigned)m, d2);
                unsigned hi = __shfl_xor_sync(0xffffffffu, (unsigned)(m >> 32), d2);
                u64 o = ((u64)hi << 32) | lo;
                if (o < m) m = o;
            }
            bi = (int)(unsigned)m;
        }

        float cbv = cbk[((size_t)i*CBN + bi)*8 + q];
        float diff = ze - cbv;
        loss_acc += diff*diff;
        if (q == 0) out[CODES_OFF + ((size_t)b*NC + i)*TT + t] = (float)bi;

        u64 stz2[4];
        #pragma unroll
        for (int m = 0; m < 4; m++){
            float lo = __shfl_sync(0xffffffffu, cbv, 8*m + r);
            float hi = __shfl_sync(0xffffffffu, cbv, 8*m + 4 + r);
            stz2[m] = pack2(lo, hi);
        }

        // out_proj + residual update (lane covers d = q + 8j); res stride 136 => conflict-free
        {
            const float* owb = sm + OW_OFF + (i&1)*1536 + q*12;
            const float* obb = sm + OBT_OFF + (i&1)*128 + q*16;
            float* rp = res_s + c*136 + q;
            #pragma unroll
            for (int m = 0; m < 4; m++){
                float4 ov = *(const float4*)(obb + 4*m);    // broadcast, 1 wf
                float obj[4] = {ov.x, ov.y, ov.z, ov.w};
                #pragma unroll
                for (int jj = 0; jj < 4; jj++){
                    int j = m*4 + jj;
                    const float* row = owb + j*96;
                    ulonglong2 p0 = *(const ulonglong2*)row;
                    ulonglong2 p1 = *(const ulonglong2*)(row + 4);
                    u64 acc = ffma2(p0.x, stz2[0], ZERO2);
                    acc = ffma2(p0.y, stz2[1], acc);
                    acc = ffma2(p1.x, stz2[2], acc);
                    acc = ffma2(p1.y, stz2[3], acc);
                    float ol, oh; unpack2(acc, ol, oh);
                    float o = (ol + oh) + obj[jj];
                    rp[8*j] -= o;
                }
            }
        }

        if (i < NC-1) stage_params(i+1, tid, sm, in_w, in_b, out_w, out_b);
        __syncthreads();   // C
    }

    // ---- z_q = z - residual_final (coalesced, z recomputed) ----
    #pragma unroll
    for (int k = 0; k < 16; k++){
        int idx = k*512 + tid;
        int d = idx >> 6, cc = idx & 63;
        int tt = t0 + cc;
        float m  = xm[(size_t)d*TT + tt];
        float s  = xs[(size_t)d*TT + tt];
        float n  = nz[(size_t)d*TT + tt];
        float sp = fmaxf(s, 0.f) + log1pf(expf(-fabsf(s)));
        float st = sp + 1e-4f;
        float z  = n*st + m;
        out[((size_t)b*DD + d)*TT + tt] = z - res_s[cc*136 + d];
    }

    // ---- loss reductions ----
    #pragma unroll
    for (int s2 = 1; s2 < 32; s2 <<= 1){
        kl_acc   += __shfl_xor_sync(0xffffffffu, kl_acc,   s2);
        loss_acc += __shfl_xor_sync(0xffffffffu, loss_acc, s2);
    }
    if (lane == 0){ red[w] = kl_acc; red[16 + w] = loss_acc; }
    __syncthreads();
    if (tid == 0){
        float ks = 0.f, ls = 0.f;
        #pragma unroll
        for (int j = 0; j < 16; j++){ ks += red[j]; ls += red[16 + j]; }
        atomicAdd(out + ZQ_N,     ks * (1.f / (float)(BB*TT)));
        float lv = ls * (1.f / (float)(BB*CD*TT*NC));
        atomicAdd(out + ZQ_N + 1, lv);   // commitment
        atomicAdd(out + ZQ_N + 2, lv);   // codebook (identical value)
    }
}

// ---------------- launch ----------------
extern "C" void kernel_launch(void* const* d_in, const int* in_sizes, int n_in,
                              void* d_out, int out_size)
{
    const float* x     = (const float*)d_in[0];
    const float* noise = (const float*)d_in[1];
    const float* in_w  = (const float*)d_in[2];
    const float* in_b  = (const float*)d_in[3];
    const float* cbk   = (const float*)d_in[4];
    const float* out_w = (const float*)d_in[5];
    const float* out_b = (const float*)d_in[6];
    float* out = (float*)d_out;

    cudaFuncSetAttribute(rvq_main, cudaFuncAttributeMaxDynamicSharedMemorySize, SMEM_BYTES);

    rvq_prep<<<(NC*CBN + 255)/256, 256>>>(cbk, out);
    rvq_main<<<NCOL/64, 512, SMEM_BYTES>>>(x, noise, in_w, in_b, cbk, out_w, out_b, out);
}

// round 14
// speedup vs baseline: 1.0022x; 1.0017x over previous
#include <cuda_runtime.h>
#include <cstdint>

// ---------------- problem constants ----------------
#define BB 16
#define TT 4096
#define DD 128
#define NC 9
#define CBN 1024
#define CD 8

#define NCOL (BB*TT)                  // 65536
#define ZQ_N (BB*DD*TT)               // 8388608
#define CODES_OFF (ZQ_N + 3)          // 8388611
#define CODES_N (BB*NC*TT)            // 589824
#define LAT_OFF (CODES_OFF + CODES_N) // 8978435

// ---------------- smem layout (float offsets) ----------------
// res[64][136], cb8[1024][8], cb2[1024], iw[8][132], ow[2][128][12],
// ib[8], obt[2][8][16], enc_t[8][68], scri u64[64][17], red[32]
#define RES_OFF  0
#define CB8_OFF  8704
#define CB2_OFF  16896
#define IW_OFF   17920
#define OW_OFF   18976
#define IB_OFF   22048
#define OBT_OFF  22056
#define ENC_OFF  22312
#define SCRI_OFF 22856
#define RED_OFF  25032
#define SMEM_FLOATS 25064
#define SMEM_BYTES (SMEM_FLOATS*4)    // 100256 B; x2 blocks = 200.5 KB <= 228 KB

// codebook scratch: rows = -2*cb_n (normalized), plus per-entry sum(cb_n^2)
__device__ __align__(16) float g_cb8[NC*CBN*8];
__device__ __align__(16) float g_cb2[NC*CBN];

typedef unsigned long long u64;

__device__ __forceinline__ u64 ffma2(u64 a, u64 b, u64 c){
    u64 d; asm("fma.rn.f32x2 %0, %1, %2, %3;" : "=l"(d) : "l"(a), "l"(b), "l"(c)); return d;
}
__device__ __forceinline__ u64 pack2(float lo, float hi){
    u64 d; asm("mov.b64 %0, {%1, %2};" : "=l"(d) : "f"(lo), "f"(hi)); return d;
}
__device__ __forceinline__ void unpack2(u64 a, float& lo, float& hi){
    asm("mov.b64 {%0, %1}, %2;" : "=f"(lo), "=f"(hi) : "l"(a));
}
// sortable key: ascending u64 order == ascending (score, entry-index)
__device__ __forceinline__ u64 mkkey(float s, int idx){
    unsigned u = __float_as_uint(s);
    u ^= ((unsigned)((int)u >> 31)) | 0x80000000u;
    return ((u64)u << 32) | (unsigned)idx;
}

// ---------------- prep: normalize codebooks (+ zero scalar outputs) ----------------
__global__ void rvq_prep(const float* __restrict__ cbk, float* __restrict__ out){
    if (blockIdx.x == 0 && threadIdx.x < 3) out[ZQ_N + threadIdx.x] = 0.f;
    int e = blockIdx.x * 256 + threadIdx.x;
    if (e >= NC*CBN) return;
    float v[8]; float s = 0.f;
    #pragma unroll
    for (int k = 0; k < 8; k++){ v[k] = cbk[(size_t)e*8 + k]; s += v[k]*v[k]; }
    float dnm = fmaxf(sqrtf(s), 1e-12f);
    float s2 = 0.f;
    #pragma unroll
    for (int k = 0; k < 8; k++){
        float w = v[k] / dnm;
        g_cb8[(size_t)e*8 + k] = -2.f * w;   // pre-scaled for the distance scan
        s2 += w*w;
    }
    g_cb2[e] = s2;
}

// stage params for codebook i (ow/ob double-buffered on i&1)
__device__ __forceinline__ void stage_params(int i, int tid, float* sm,
    const float* __restrict__ in_w, const float* __restrict__ in_b,
    const float* __restrict__ out_w, const float* __restrict__ out_b)
{
    float4* dst4 = (float4*)(sm + CB8_OFF);
    const float4* src4 = (const float4*)(g_cb8 + (size_t)i*CBN*8);
    #pragma unroll
    for (int k = 0; k < 4; k++) dst4[tid + k*512] = src4[tid + k*512];
    if (tid < 256)
        ((float4*)(sm + CB2_OFF))[tid] = ((const float4*)(g_cb2 + (size_t)i*CBN))[tid];
    #pragma unroll
    for (int k = 0; k < 2; k++){
        int idx = k*512 + tid;
        sm[IW_OFF + (idx>>7)*132 + (idx&127)] = in_w[(size_t)i*1024 + idx];
        sm[OW_OFF + (i&1)*1536 + (idx>>3)*12 + (idx&7)] = out_w[(size_t)i*1024 + idx];
    }
    if (tid < 8)   sm[IB_OFF + tid] = in_b[i*8 + tid];
    if (tid < 128) sm[OBT_OFF + (i&1)*128 + (tid&7)*16 + (tid>>3)] = out_b[i*128 + tid];
}

// ---------------- main kernel ----------------
// grid 1024 x 512 threads; block = 64 consecutive t-columns of one batch b.
__global__ __launch_bounds__(512, 2)
void rvq_main(const float* __restrict__ x, const float* __restrict__ noise,
              const float* __restrict__ in_w, const float* __restrict__ in_b,
              const float* __restrict__ cbk, const float* __restrict__ out_w,
              const float* __restrict__ out_b, float* __restrict__ out)
{
    extern __shared__ float sm[];
    float* res_s = sm + RES_OFF;
    float* cb8_s = sm + CB8_OFF;
    float* cb2_s = sm + CB2_OFF;
    float* enc_t = sm + ENC_OFF;
    u64*   scri  = (u64*)(sm + SCRI_OFF);
    float* red   = sm + RED_OFF;

    const int tid  = threadIdx.x;
    const int bidx = blockIdx.x;
    const int b    = bidx >> 6;
    const int t0   = (bidx & 63) * 64;
    const int lane = tid & 31;
    const int w    = tid >> 5;
    const int r    = lane & 3;     // column-within-warp
    const int q    = lane >> 2;    // codebook-dim / d-group
    const int c    = w*4 + r;      // this lane's column within block
    const int t    = t0 + c;

    float kl_acc = 0.f, loss_acc = 0.f;

    const float* xm = x + ((size_t)b*256)*TT;
    const float* xs = x + ((size_t)b*256 + 128)*TT;
    const float* nz = noise + ((size_t)b*128)*TT;

    // ---- prologue: stage codebook 0 + z init (coalesced) + KL ----
    stage_params(0, tid, sm, in_w, in_b, out_w, out_b);
    #pragma unroll
    for (int k = 0; k < 16; k++){
        int idx = k*512 + tid;
        int d = idx >> 6, cc = idx & 63;
        int tt = t0 + cc;
        float m  = xm[(size_t)d*TT + tt];
        float s  = xs[(size_t)d*TT + tt];
        float n  = nz[(size_t)d*TT + tt];
        float sp = fmaxf(s, 0.f) + log1pf(expf(-fabsf(s)));
        float st = sp + 1e-4f;
        float var = st*st;
        kl_acc += m*m + var - logf(var) - 1.f;
        res_s[cc*136 + d] = n*st + m;
    }
    __syncthreads();

    const u64 ZERO2 = pack2(0.f, 0.f);

    for (int i = 0; i < NC; i++){
        // ========== phase 1: in_proj + normalize + publish enc ==========
        float ze;
        {
            const ulonglong2* wr = (const ulonglong2*)(sm + IW_OFF + q*132);
            const ulonglong2* rr = (const ulonglong2*)(res_s + c*136);
            u64 a0 = ZERO2, a1 = ZERO2;
            #pragma unroll 8
            for (int k = 0; k < 32; k++){
                ulonglong2 wv = wr[k], rv = rr[k];
                a0 = ffma2(wv.x, rv.x, a0);
                a1 = ffma2(wv.y, rv.y, a1);
            }
            float l0,h0,l1,h1; unpack2(a0,l0,h0); unpack2(a1,l1,h1);
            ze = (l0+l1) + (h0+h1) + sm[IB_OFF + q];
        }
        float ss = ze*ze;
        ss += __shfl_xor_sync(0xffffffffu, ss, 4);
        ss += __shfl_xor_sync(0xffffffffu, ss, 8);
        ss += __shfl_xor_sync(0xffffffffu, ss, 16);
        float en = ze / fmaxf(sqrtf(ss), 1e-12f);

        enc_t[q*68 + c] = en;                               // 1-wf STS (4q+r perm)
        out[LAT_OFF + ((size_t)b*(NC*CD) + i*CD + q)*TT + t] = ze;
        __syncthreads();   // A

        // ========== phase 2: scan (warp w owns entries [64w,64w+64)) ==========
        {
            u64 eA[4], eB[4];
            #pragma unroll
            for (int k = 0; k < 4; k++){
                float a0 = enc_t[(2*k)*68 + lane],      a1 = enc_t[(2*k+1)*68 + lane];
                float b0 = enc_t[(2*k)*68 + lane + 32], b1 = enc_t[(2*k+1)*68 + lane + 32];
                eA[k] = pack2(a0, a1); eB[k] = pack2(b0, b1);
            }
            const float* base8 = cb8_s + (w*64)*8;
            const float* b2    = cb2_s + w*64;
            float bestA = 3.4e38f, bestB = 3.4e38f;
            int bjA = 0, bjB = 0;
            #pragma unroll 2
            for (int j4 = 0; j4 < 16; j4++){
                float4 s4 = *(const float4*)(b2 + j4*4);    // broadcast, 1 wf per 4 entries
                float s2a[4] = {s4.x, s4.y, s4.z, s4.w};
                #pragma unroll
                for (int m = 0; m < 4; m++){
                    int j = j4*4 + m;
                    const float* row = base8 + j*8;         // uniform -> broadcast
                    ulonglong2 p0 = *(const ulonglong2*)row;
                    ulonglong2 p1 = *(const ulonglong2*)(row + 4);
                    u64 c0 = pack2(s2a[m], 0.f);            // acc init = (sum cb_n^2, 0)

                    u64 aA = ffma2(p0.x, eA[0], c0);
                    aA = ffma2(p0.y, eA[1], aA);
                    aA = ffma2(p1.x, eA[2], aA);
                    aA = ffma2(p1.y, eA[3], aA);
                    float al, ah; unpack2(aA, al, ah);
                    float sA = al + ah;
                    if (sA < bestA){ bestA = sA; bjA = j; }

                    u64 aB = ffma2(p0.x, eB[0], c0);
                    aB = ffma2(p0.y, eB[1], aB);
                    aB = ffma2(p1.x, eB[2], aB);
                    aB = ffma2(p1.y, eB[3], aB);
                    float bl, bh; unpack2(aB, bl, bh);
                    float sB = bl + bh;
                    if (sB < bestB){ bestB = sB; bjB = j; }
                }
            }
            scri[lane*17 + w]      = mkkey(bestA, (w<<6) | bjA);
            scri[(lane+32)*17 + w] = mkkey(bestB, (w<<6) | bjB);
        }
        __syncthreads();   // B

        // ========== phase 3: per-warp argmin combine + outputs + out_proj (+ stage next) ==========
        int bi;
        {
            // lane (q,r): slot q and q+8 of column c = 4w+r
            const u64* sp = scri + (size_t)c*17;
            u64 m0 = sp[q], m1 = sp[q+8];
            u64 m  = (m1 < m0) ? m1 : m0;
            #pragma unroll
            for (int d2 = 4; d2 <= 16; d2 <<= 1){
                unsigned lo = __shfl_xor_sync(0xffffffffu, (unsigned)m, d2);
                unsigned hi = __shfl_xor_sync(0xffffffffu, (unsigned)(m >> 32), d2);
                u64 o = ((u64)hi << 32) | lo;
                if (o < m) m = o;
            }
            bi = (int)(unsigned)m;
        }

        float cbv = cbk[((size_t)i*CBN + bi)*8 + q];
        float diff = ze - cbv;
        loss_acc += diff*diff;
        if (q == 0) out[CODES_OFF + ((size_t)b*NC + i)*TT + t] = (float)bi;

        u64 stz2[4];
        #pragma unroll
        for (int m = 0; m < 4; m++){
            float lo = __shfl_sync(0xffffffffu, cbv, 8*m + r);
            float hi = __shfl_sync(0xffffffffu, cbv, 8*m + 4 + r);
            stz2[m] = pack2(lo, hi);
        }

        // out_proj + residual update (lane covers d = q + 8j); res stride 136 => conflict-free
        {
            const float* owb = sm + OW_OFF + (i&1)*1536 + q*12;
            const float* obb = sm + OBT_OFF + (i&1)*128 + q*16;
            float* rp = res_s + c*136 + q;
            #pragma unroll
            for (int m = 0; m < 4; m++){
                float4 ov = *(const float4*)(obb + 4*m);    // broadcast, 1 wf
                float obj[4] = {ov.x, ov.y, ov.z, ov.w};
                #pragma unroll
                for (int jj = 0; jj < 4; jj++){
                    int j = m*4 + jj;
                    const float* row = owb + j*96;
                    ulonglong2 p0 = *(const ulonglong2*)row;
                    ulonglong2 p1 = *(const ulonglong2*)(row + 4);
                    u64 acc = ffma2(p0.x, stz2[0], ZERO2);
                    acc = ffma2(p0.y, stz2[1], acc);
                    acc = ffma2(p1.x, stz2[2], acc);
                    acc = ffma2(p1.y, stz2[3], acc);
                    float ol, oh; unpack2(acc, ol, oh);
                    float o = (ol + oh) + obj[jj];
                    rp[8*j] -= o;
                }
            }
        }

        if (i < NC-1) stage_params(i+1, tid, sm, in_w, in_b, out_w, out_b);
        __syncthreads();   // C
    }

    // ---- z_q = z - residual_final (coalesced, z recomputed) ----
    #pragma unroll
    for (int k = 0; k < 16; k++){
        int idx = k*512 + tid;
        int d = idx >> 6, cc = idx & 63;
        int tt = t0 + cc;
        float m  = xm[(size_t)d*TT + tt];
        float s  = xs[(size_t)d*TT + tt];
        float n  = nz[(size_t)d*TT + tt];
        float sp = fmaxf(s, 0.f) + log1pf(expf(-fabsf(s)));
        float st = sp + 1e-4f;
        float z  = n*st + m;
        out[((size_t)b*DD + d)*TT + tt] = z - res_s[cc*136 + d];
    }

    // ---- loss reductions ----
    #pragma unroll
    for (int s2 = 1; s2 < 32; s2 <<= 1){
        kl_acc   += __shfl_xor_sync(0xffffffffu, kl_acc,   s2);
        loss_acc += __shfl_xor_sync(0xffffffffu, loss_acc, s2);
    }
    if (lane == 0){ red[w] = kl_acc; red[16 + w] = loss_acc; }
    __syncthreads();
    if (tid == 0){
        float ks = 0.f, ls = 0.f;
        #pragma unroll
        for (int j = 0; j < 16; j++){ ks += red[j]; ls += red[16 + j]; }
        atomicAdd(out + ZQ_N,     ks * (1.f / (float)(BB*TT)));
        float lv = ls * (1.f / (float)(BB*CD*TT*NC));
        atomicAdd(out + ZQ_N + 1, lv);   // commitment
        atomicAdd(out + ZQ_N + 2, lv);   // codebook (identical value)
    }
}

// ---------------- launch ----------------
extern "C" void kernel_launch(void* const* d_in, const int* in_sizes, int n_in,
                              void* d_out, int out_size)
{
    const float* x     = (const float*)d_in[0];
    const float* noise = (const float*)d_in[1];
    const float* in_w  = (const float*)d_in[2];
    const float* in_b  = (const float*)d_in[3];
    const float* cbk   = (const float*)d_in[4];
    const float* out_w = (const float*)d_in[5];
    const float* out_b = (const float*)d_in[6];
    float* out = (float*)d_out;

    cudaFuncSetAttribute(rvq_main, cudaFuncAttributeMaxDynamicSharedMemorySize, SMEM_BYTES);

    rvq_prep<<<(NC*CBN + 255)/256, 256>>>(cbk, out);
    rvq_main<<<NCOL/64, 512, SMEM_BYTES>>>(x, noise, in_w, in_b, cbk, out_w, out_b, out);
}

// round 15
// speedup vs baseline: 1.0027x; 1.0004x over previous
#include <cuda_runtime.h>
#include <cstdint>

// ---------------- problem constants ----------------
#define BB 16
#define TT 4096
#define DD 128
#define NC 9
#define CBN 1024
#define CD 8

#define NCOL (BB*TT)                  // 65536
#define ZQ_N (BB*DD*TT)               // 8388608
#define CODES_OFF (ZQ_N + 3)          // 8388611
#define CODES_N (BB*NC*TT)            // 589824
#define LAT_OFF (CODES_OFF + CODES_N) // 8978435

// ---------------- smem layout (float offsets) ----------------
// res[64][136], cb8[1024][8], cb2[1024], iw[8][132], ow[2][128][12],
// ib[8], obt[2][8][16], enc_t[8][68], scri u64[64][17], red[32]
#define RES_OFF  0
#define CB8_OFF  8704
#define CB2_OFF  16896
#define IW_OFF   17920
#define OW_OFF   18976
#define IB_OFF   22048
#define OBT_OFF  22056
#define ENC_OFF  22312
#define SCRI_OFF 22856
#define RED_OFF  25032
#define SMEM_FLOATS 25064
#define SMEM_BYTES (SMEM_FLOATS*4)    // 100256 B; x2 blocks = 200.5 KB <= 228 KB

// codebook scratch: rows = -2*cb_n (normalized), plus per-entry sum(cb_n^2)
__device__ __align__(16) float g_cb8[NC*CBN*8];
__device__ __align__(16) float g_cb2[NC*CBN];

typedef unsigned long long u64;

__device__ __forceinline__ u64 ffma2(u64 a, u64 b, u64 c){
    u64 d; asm("fma.rn.f32x2 %0, %1, %2, %3;" : "=l"(d) : "l"(a), "l"(b), "l"(c)); return d;
}
__device__ __forceinline__ u64 pack2(float lo, float hi){
    u64 d; asm("mov.b64 %0, {%1, %2};" : "=l"(d) : "f"(lo), "f"(hi)); return d;
}
__device__ __forceinline__ void unpack2(u64 a, float& lo, float& hi){
    asm("mov.b64 {%0, %1}, %2;" : "=f"(lo), "=f"(hi) : "l"(a));
}
// sortable key: ascending u64 order == ascending (score, entry-index)
__device__ __forceinline__ u64 mkkey(float s, int idx){
    unsigned u = __float_as_uint(s);
    u ^= ((unsigned)((int)u >> 31)) | 0x80000000u;
    return ((u64)u << 32) | (unsigned)idx;
}

// ---------------- prep: normalize codebooks (+ zero scalar outputs) ----------------
__global__ void rvq_prep(const float* __restrict__ cbk, float* __restrict__ out){
    if (blockIdx.x == 0 && threadIdx.x < 3) out[ZQ_N + threadIdx.x] = 0.f;
    int e = blockIdx.x * 256 + threadIdx.x;
    if (e >= NC*CBN) return;
    float v[8]; float s = 0.f;
    #pragma unroll
    for (int k = 0; k < 8; k++){ v[k] = cbk[(size_t)e*8 + k]; s += v[k]*v[k]; }
    float dnm = fmaxf(sqrtf(s), 1e-12f);
    float s2 = 0.f;
    #pragma unroll
    for (int k = 0; k < 8; k++){
        float w = v[k] / dnm;
        g_cb8[(size_t)e*8 + k] = -2.f * w;   // pre-scaled for the distance scan
        s2 += w*w;
    }
    g_cb2[e] = s2;
}

// stage params for codebook i (ow/ob double-buffered on i&1)
__device__ __forceinline__ void stage_params(int i, int tid, float* sm,
    const float* __restrict__ in_w, const float* __restrict__ in_b,
    const float* __restrict__ out_w, const float* __restrict__ out_b)
{
    float4* dst4 = (float4*)(sm + CB8_OFF);
    const float4* src4 = (const float4*)(g_cb8 + (size_t)i*CBN*8);
    #pragma unroll
    for (int k = 0; k < 4; k++) dst4[tid + k*512] = src4[tid + k*512];
    if (tid < 256)
        ((float4*)(sm + CB2_OFF))[tid] = ((const float4*)(g_cb2 + (size_t)i*CBN))[tid];
    #pragma unroll
    for (int k = 0; k < 2; k++){
        int idx = k*512 + tid;
        sm[IW_OFF + (idx>>7)*132 + (idx&127)] = in_w[(size_t)i*1024 + idx];
        sm[OW_OFF + (i&1)*1536 + (idx>>3)*12 + (idx&7)] = out_w[(size_t)i*1024 + idx];
    }
    if (tid < 8)   sm[IB_OFF + tid] = in_b[i*8 + tid];
    if (tid < 128) sm[OBT_OFF + (i&1)*128 + (tid&7)*16 + (tid>>3)] = out_b[i*128 + tid];
}

// ---------------- main kernel ----------------
// grid 1024 x 512 threads; block = 64 consecutive t-columns of one batch b.
__global__ __launch_bounds__(512, 2)
void rvq_main(const float* __restrict__ x, const float* __restrict__ noise,
              const float* __restrict__ in_w, const float* __restrict__ in_b,
              const float* __restrict__ cbk, const float* __restrict__ out_w,
              const float* __restrict__ out_b, float* __restrict__ out)
{
    extern __shared__ float sm[];
    float* res_s = sm + RES_OFF;
    float* cb8_s = sm + CB8_OFF;
    float* cb2_s = sm + CB2_OFF;
    float* enc_t = sm + ENC_OFF;
    u64*   scri  = (u64*)(sm + SCRI_OFF);
    float* red   = sm + RED_OFF;

    const int tid  = threadIdx.x;
    const int bidx = blockIdx.x;
    const int b    = bidx >> 6;
    const int t0   = (bidx & 63) * 64;
    const int lane = tid & 31;
    const int w    = tid >> 5;
    const int r    = lane & 3;     // column-within-warp
    const int q    = lane >> 2;    // codebook-dim / d-group
    const int c    = w*4 + r;      // this lane's column within block
    const int t    = t0 + c;

    float kl_acc = 0.f, loss_acc = 0.f;

    const float* xm = x + ((size_t)b*256)*TT;
    const float* xs = x + ((size_t)b*256 + 128)*TT;
    const float* nz = noise + ((size_t)b*128)*TT;

    // ---- prologue: stage codebook 0 + z init (coalesced) + KL ----
    stage_params(0, tid, sm, in_w, in_b, out_w, out_b);
    #pragma unroll
    for (int k = 0; k < 16; k++){
        int idx = k*512 + tid;
        int d = idx >> 6, cc = idx & 63;
        int tt = t0 + cc;
        float m  = xm[(size_t)d*TT + tt];
        float s  = xs[(size_t)d*TT + tt];
        float n  = nz[(size_t)d*TT + tt];
        float sp = fmaxf(s, 0.f) + log1pf(expf(-fabsf(s)));
        float st = sp + 1e-4f;
        float var = st*st;
        kl_acc += m*m + var - logf(var) - 1.f;
        res_s[cc*136 + d] = n*st + m;
    }
    __syncthreads();

    const u64 ZERO2 = pack2(0.f, 0.f);

    for (int i = 0; i < NC; i++){
        // ========== phase 1: in_proj + normalize + publish enc ==========
        float ze;
        {
            const ulonglong2* wr = (const ulonglong2*)(sm + IW_OFF + q*132);
            const ulonglong2* rr = (const ulonglong2*)(res_s + c*136);
            u64 a0 = ZERO2, a1 = ZERO2;
            #pragma unroll 8
            for (int k = 0; k < 32; k++){
                ulonglong2 wv = wr[k], rv = rr[k];
                a0 = ffma2(wv.x, rv.x, a0);
                a1 = ffma2(wv.y, rv.y, a1);
            }
            float l0,h0,l1,h1; unpack2(a0,l0,h0); unpack2(a1,l1,h1);
            ze = (l0+l1) + (h0+h1) + sm[IB_OFF + q];
        }
        float ss = ze*ze;
        ss += __shfl_xor_sync(0xffffffffu, ss, 4);
        ss += __shfl_xor_sync(0xffffffffu, ss, 8);
        ss += __shfl_xor_sync(0xffffffffu, ss, 16);
        float en = ze / fmaxf(sqrtf(ss), 1e-12f);

        enc_t[q*68 + c] = en;                               // 1-wf STS (4q+r perm)
        out[LAT_OFF + ((size_t)b*(NC*CD) + i*CD + q)*TT + t] = ze;
        __syncthreads();   // A

        // ========== phase 2: scan (warp w owns entries [64w,64w+64)) ==========
        {
            u64 eA[4], eB[4];
            #pragma unroll
            for (int k = 0; k < 4; k++){
                float a0 = enc_t[(2*k)*68 + lane],      a1 = enc_t[(2*k+1)*68 + lane];
                float b0 = enc_t[(2*k)*68 + lane + 32], b1 = enc_t[(2*k+1)*68 + lane + 32];
                eA[k] = pack2(a0, a1); eB[k] = pack2(b0, b1);
            }
            const float* base8 = cb8_s + (w*64)*8;
            const float* b2    = cb2_s + w*64;
            float bestA = 3.4e38f, bestB = 3.4e38f;
            int bjA = 0, bjB = 0;
            #pragma unroll 2
            for (int j4 = 0; j4 < 16; j4++){
                float4 s4 = *(const float4*)(b2 + j4*4);    // broadcast, 1 wf per 4 entries
                float s2a[4] = {s4.x, s4.y, s4.z, s4.w};
                #pragma unroll
                for (int m = 0; m < 4; m++){
                    int j = j4*4 + m;
                    const float* row = base8 + j*8;         // uniform -> broadcast
                    ulonglong2 p0 = *(const ulonglong2*)row;
                    ulonglong2 p1 = *(const ulonglong2*)(row + 4);
                    u64 c0 = pack2(s2a[m], 0.f);            // acc init = (sum cb_n^2, 0)

                    u64 aA = ffma2(p0.x, eA[0], c0);
                    aA = ffma2(p0.y, eA[1], aA);
                    aA = ffma2(p1.x, eA[2], aA);
                    aA = ffma2(p1.y, eA[3], aA);
                    float al, ah; unpack2(aA, al, ah);
                    float sA = al + ah;
                    if (sA < bestA){ bestA = sA; bjA = j; }

                    u64 aB = ffma2(p0.x, eB[0], c0);
                    aB = ffma2(p0.y, eB[1], aB);
                    aB = ffma2(p1.x, eB[2], aB);
                    aB = ffma2(p1.y, eB[3], aB);
                    float bl, bh; unpack2(aB, bl, bh);
                    float sB = bl + bh;
                    if (sB < bestB){ bestB = sB; bjB = j; }
                }
            }
            scri[lane*17 + w]      = mkkey(bestA, (w<<6) | bjA);
            scri[(lane+32)*17 + w] = mkkey(bestB, (w<<6) | bjB);
        }
        __syncthreads();   // B

        // ========== phase 3: per-warp argmin combine + outputs + out_proj (+ stage next) ==========
        int bi;
        {
            // lane (q,r): slot q and q+8 of column c = 4w+r
            const u64* sp = scri + (size_t)c*17;
            u64 m0 = sp[q], m1 = sp[q+8];
            u64 m  = (m1 < m0) ? m1 : m0;
            #pragma unroll
            for (int d2 = 4; d2 <= 16; d2 <<= 1){
                unsigned lo = __shfl_xor_sync(0xffffffffu, (unsigned)m, d2);
                unsigned hi = __shfl_xor_sync(0xffffffffu, (unsigned)(m >> 32), d2);
                u64 o = ((u64)hi << 32) | lo;
                if (o < m) m = o;
            }
            bi = (int)(unsigned)m;
        }

        float cbv = cbk[((size_t)i*CBN + bi)*8 + q];
        float diff = ze - cbv;
        loss_acc += diff*diff;
        if (q == 0) out[CODES_OFF + ((size_t)b*NC + i)*TT + t] = (float)bi;

        u64 stz2[4];
        #pragma unroll
        for (int m = 0; m < 4; m++){
            float lo = __shfl_sync(0xffffffffu, cbv, 8*m + r);
            float hi = __shfl_sync(0xffffffffu, cbv, 8*m + 4 + r);
            stz2[m] = pack2(lo, hi);
        }

        // out_proj + residual update (lane covers d = q + 8j); res stride 136 => conflict-free
        {
            const float* owb = sm + OW_OFF + (i&1)*1536 + q*12;
            const float* obb = sm + OBT_OFF + (i&1)*128 + q*16;
            float* rp = res_s + c*136 + q;
            #pragma unroll
            for (int m = 0; m < 4; m++){
                float4 ov = *(const float4*)(obb + 4*m);    // broadcast, 1 wf
                float obj[4] = {ov.x, ov.y, ov.z, ov.w};
                #pragma unroll
                for (int jj = 0; jj < 4; jj++){
                    int j = m*4 + jj;
                    const float* row = owb + j*96;
                    ulonglong2 p0 = *(const ulonglong2*)row;
                    ulonglong2 p1 = *(const ulonglong2*)(row + 4);
                    u64 acc = ffma2(p0.x, stz2[0], ZERO2);
                    acc = ffma2(p0.y, stz2[1], acc);
                    acc = ffma2(p1.x, stz2[2], acc);
                    acc = ffma2(p1.y, stz2[3], acc);
                    float ol, oh; unpack2(acc, ol, oh);
                    float o = (ol + oh) + obj[jj];
                    rp[8*j] -= o;
                }
            }
        }

        if (i < NC-1) stage_params(i+1, tid, sm, in_w, in_b, out_w, out_b);
        __syncthreads();   // C
    }

    // ---- z_q = z - residual_final (coalesced, z recomputed) ----
    #pragma unroll
    for (int k = 0; k < 16; k++){
        int idx = k*512 + tid;
        int d = idx >> 6, cc = idx & 63;
        int tt = t0 + cc;
        float m  = xm[(size_t)d*TT + tt];
        float s  = xs[(size_t)d*TT + tt];
        float n  = nz[(size_t)d*TT + tt];
        float sp = fmaxf(s, 0.f) + log1pf(expf(-fabsf(s)));
        float st = sp + 1e-4f;
        float z  = n*st + m;
        out[((size_t)b*DD + d)*TT + tt] = z - res_s[cc*136 + d];
    }

    // ---- loss reductions ----
    #pragma unroll
    for (int s2 = 1; s2 < 32; s2 <<= 1){
        kl_acc   += __shfl_xor_sync(0xffffffffu, kl_acc,   s2);
        loss_acc += __shfl_xor_sync(0xffffffffu, loss_acc, s2);
    }
    if (lane == 0){ red[w] = kl_acc; red[16 + w] = loss_acc; }
    __syncthreads();
    if (tid == 0){
        float ks = 0.f, ls = 0.f;
        #pragma unroll
        for (int j = 0; j < 16; j++){ ks += red[j]; ls += red[16 + j]; }
        atomicAdd(out + ZQ_N,     ks * (1.f / (float)(BB*TT)));
        float lv = ls * (1.f / (float)(BB*CD*TT*NC));
        atomicAdd(out + ZQ_N + 1, lv);   // commitment
        atomicAdd(out + ZQ_N + 2, lv);   // codebook (identical value)
    }
}

// ---------------- launch ----------------
extern "C" void kernel_launch(void* const* d_in, const int* in_sizes, int n_in,
                              void* d_out, int out_size)
{
    const float* x     = (const float*)d_in[0];
    const float* noise = (const float*)d_in[1];
    const float* in_w  = (const float*)d_in[2];
    const float* in_b  = (const float*)d_in[3];
    const float* cbk   = (const float*)d_in[4];
    const float* out_w = (const float*)d_in[5];
    const float* out_b = (const float*)d_in[6];
    float* out = (float*)d_out;

    cudaFuncSetAttribute(rvq_main, cudaFuncAttributeMaxDynamicSharedMemorySize, SMEM_BYTES);

    rvq_prep<<<(NC*CBN + 255)/256, 256>>>(cbk, out);
    rvq_main<<<NCOL/64, 512, SMEM_BYTES>>>(x, noise, in_w, in_b, cbk, out_w, out_b, out);
}